// round 15
// baseline (speedup 1.0000x reference)
#include <cuda_runtime.h>
#include <cuda_bf16.h>
#include <cstdint>

// Problem constants
#define BN   32
#define DN   256
#define KN   1024
#define HWN  1024
#define NN   32768

#define LIST_CAP 32
#define CAND_MAX 32
#define MARGIN   4.0e-3f   // > 2x worst-case bf16 score error (~1.6e-3)

// ---------------------------------------------------------------------------
// Device-global scratch (no allocation allowed)
__device__ unsigned long long g_best[NN];
__device__ float g_w2[KN];
__device__ float g_x2[NN];
__device__ __nv_bfloat16 g_xb[NN * DN];       // x bf16, PAIR-PERMUTED rows [n][pd]
__device__ float g_xt[NN * DN];               // x transposed fp32 [n][d]
__device__ int g_ccnt[NN];
__device__ unsigned int g_cand[NN * CAND_MAX];
__device__ uint2 g_bf[8 * 16 * 16 * 32];      // fragment-major bf16 codebook (512KB)

// ---------------------------------------------------------------------------
__device__ __forceinline__ uint32_t smem_u32(const void* p) {
    uint32_t a;
    asm("{ .reg .u64 t; cvta.to.shared.u64 t, %1; cvt.u32.u64 %0, t; }" : "=r"(a) : "l"(p));
    return a;
}
__device__ __forceinline__ void mma16816(float* c, uint32_t a0, uint32_t a1,
                                         uint32_t a2, uint32_t a3,
                                         uint32_t b0, uint32_t b1) {
    asm volatile(
        "mma.sync.aligned.m16n8k16.row.col.f32.bf16.bf16.f32 "
        "{%0,%1,%2,%3}, {%4,%5,%6,%7}, {%8,%9}, {%0,%1,%2,%3};"
        : "+f"(c[0]), "+f"(c[1]), "+f"(c[2]), "+f"(c[3])
        : "r"(a0), "r"(a1), "r"(a2), "r"(a3), "r"(b0), "r"(b1));
}
#define CP16(saddr, gptr) \
    asm volatile("cp.async.cg.shared.global [%0], [%1], 16;" :: "r"(saddr), "l"(gptr) : "memory")
#define CP_COMMIT() asm volatile("cp.async.commit_group;" ::: "memory")
#define CP_WAIT0()  asm volatile("cp.async.wait_group 0;" ::: "memory")

__device__ __forceinline__ uint32_t pack_bf16x2(float lo, float hi) {
    uint16_t l = __bfloat16_as_ushort(__float2bfloat16(lo));
    uint16_t h = __bfloat16_as_ushort(__float2bfloat16(hi));
    return (uint32_t)l | ((uint32_t)h << 16);
}

// ---------------------------------------------------------------------------
// w2[k] = sum_d w[k,d]^2 (square-then-add, matching reference)
__global__ void vq_w2(const float* __restrict__ w) {
    int k = blockIdx.x * 8 + (threadIdx.x >> 5);
    int lane = threadIdx.x & 31;
    if (k >= KN) return;
    const float* row = w + (size_t)k * DN;
    float s = 0.f;
    #pragma unroll
    for (int d = lane; d < DN; d += 32) {
        float v = row[d];
        s = __fadd_rn(s, __fmul_rn(v, v));
    }
    #pragma unroll
    for (int o = 16; o > 0; o >>= 1) s += __shfl_xor_sync(0xffffffffu, s, o);
    if (lane == 0) g_w2[k] = s;
}

// x2[n] = sum_d x[b,d,hw]^2  (only P3 needs it; runs after P1)
__global__ void vq_x2(const float* __restrict__ x) {
    int b  = blockIdx.y;
    int hw = blockIdx.x * blockDim.x + threadIdx.x;
    const float* base = x + (size_t)b * DN * HWN + hw;
    float s = 0.f;
    #pragma unroll 8
    for (int d = 0; d < DN; d++) {
        float v = base[(size_t)d * HWN];
        s = __fadd_rn(s, __fmul_rn(v, v));
    }
    g_x2[b * HWN + hw] = s;
}

// Fragment-major bf16 codebook: g_bf[((c*16+ks)*16+nt)*32+lane] = {b0,b1}
__global__ void vq_wfrag(const float* __restrict__ w) {
    int i = blockIdx.x * 256 + threadIdx.x;   // 0..65535
    int lane = i & 31, nt = (i >> 5) & 15, ks = (i >> 9) & 15, c = i >> 13;
    int gid = lane >> 2, tq = lane & 3;
    int k = c * 128 + nt * 8 + gid;
    const float* row = w + (size_t)k * DN + ks * 16;
    uint32_t b0 = pack_bf16x2(row[2 * tq], row[2 * tq + 1]);
    uint32_t b1 = pack_bf16x2(row[2 * tq + 8], row[2 * tq + 9]);
    g_bf[i] = make_uint2(b0, b1);
}

// Transpose x[b][d][hw] -> g_xt[n][d] fp32 and g_xb[n][pd] bf16 pair-permuted:
// pd = ks*16 + tq*4 + hi*2 + par where d = ks*16 + hi*8 + tq*2 + par.
__global__ void vq_xt(const float* __restrict__ x) {
    __shared__ float t[32][33];
    int b   = blockIdx.z;
    int d0  = blockIdx.y * 32;
    int hw0 = blockIdx.x * 32;
    int tx = threadIdx.x, ty = threadIdx.y;  // 32 x 8
    #pragma unroll
    for (int r = 0; r < 4; r++)
        t[ty + 8 * r][tx] = x[(size_t)b * DN * HWN + (size_t)(d0 + ty + 8 * r) * HWN + hw0 + tx];
    __syncthreads();
    #pragma unroll
    for (int r = 0; r < 4; r++) {
        int n = b * HWN + hw0 + ty + 8 * r;
        int d = d0 + tx;
        float v = t[tx][ty + 8 * r];
        g_xt[(size_t)n * DN + d] = v;
        int pd = (d & ~15) | (((d >> 1) & 3) << 2) | (((d >> 3) & 1) << 1) | (d & 1);
        g_xb[(size_t)n * DN + pd] = __float2bfloat16(v);
    }
}

// ---------------------------------------------------------------------------
// P1: bf16 HMMA approx score s = w2 - 2*dot (rank-equivalent to d2) + candidate
// emission. 128 CTAs x 512 thr (16 warps, 256 queries) -> ONE wave on 148 SMs.
// Warp wid -> 16 query rows; chunk processed in two 8-n-tile halves (acc = 32
// regs; A frags 64 regs -> no spill at 512 thr). cp.async double-buffered B.
#define SMB0  0
#define SMB1  65536
#define SMW2  131072
#define SMCM  135168
#define SMCC  136192
#define SMLS  137216
#define SMEM_P1 202752   // lists: 256*32*8 = 65536

__global__ __launch_bounds__(512, 1) void vq_p1() {
    extern __shared__ __align__(16) char smem[];
    float* w2s   = (float*)(smem + SMW2);
    int*   cminI = (int*)(smem + SMCM);
    int*   ccnt  = (int*)(smem + SMCC);
    uint2* clist = (uint2*)(smem + SMLS);
    const uint32_t sb = smem_u32(smem);

    const int tid  = threadIdx.x;
    const int wid  = tid >> 5, lane = tid & 31;
    const int gid  = lane >> 2, tq = lane & 3;
    const int m0   = blockIdx.x * 256;
    const int ra   = wid * 16 + gid, rb = ra + 8;

    // Prologue: start async fill of B chunk 0 (64KB)
    {
        const char* src = (const char*)g_bf;
        #pragma unroll
        for (int j = 0; j < 8; j++)
            CP16(sb + SMB0 + (tid + j * 512) * 16, src + (tid + j * 512) * 16);
        CP_COMMIT();
    }

    // Preload A fragments into registers (pair-permuted g_xb rows)
    uint2 afA[16], afB[16];
    {
        const __nv_bfloat16* pa = g_xb + (size_t)(m0 + ra) * DN + tq * 4;
        const __nv_bfloat16* pb = g_xb + (size_t)(m0 + rb) * DN + tq * 4;
        #pragma unroll
        for (int ks = 0; ks < 16; ks++) {
            afA[ks] = *(const uint2*)(pa + ks * 16);
            afB[ks] = *(const uint2*)(pb + ks * 16);
        }
    }

    #pragma unroll
    for (int i = tid; i < KN; i += 512) w2s[i] = g_w2[i];
    if (tid < 256) { cminI[tid] = 0x7F7FFFFF; ccnt[tid] = 0; }

    for (int c = 0; c < 8; c++) {
        CP_WAIT0();
        __syncthreads();   // B[c] + (c==0: inits) visible; prev compute done

        if (c < 7) {       // prefetch B[c+1] into the other buffer
            const char* src = (const char*)(g_bf + (size_t)(c + 1) * 8192);
            uint32_t dstb = sb + (((c + 1) & 1) ? SMB1 : SMB0);
            #pragma unroll
            for (int j = 0; j < 8; j++)
                CP16(dstb + (tid + j * 512) * 16, src + (tid + j * 512) * 16);
            CP_COMMIT();
        }

        const uint2* Bbuf = (const uint2*)(smem + ((c & 1) ? SMB1 : SMB0));

        #pragma unroll
        for (int half = 0; half < 2; half++) {
            float acc[8][4];
            #pragma unroll
            for (int nt = 0; nt < 8; nt++)
                acc[nt][0] = acc[nt][1] = acc[nt][2] = acc[nt][3] = 0.f;

            #pragma unroll
            for (int ks = 0; ks < 16; ks++) {
                const uint2* bp = Bbuf + (size_t)(ks * 16 + half * 8) * 32 + lane;
                #pragma unroll
                for (int nt = 0; nt < 8; nt++) {
                    uint2 b = bp[nt * 32];
                    mma16816(acc[nt], afA[ks].x, afB[ks].x, afA[ks].y, afB[ks].y, b.x, b.y);
                }
            }

            // Scores s = w2 - 2*dot; half-local row mins
            float mna = 3.4e38f, mnb = 3.4e38f;
            #pragma unroll
            for (int nt = 0; nt < 8; nt++) {
                int col = c * 128 + (half * 8 + nt) * 8 + tq * 2;
                float w20 = w2s[col], w21 = w2s[col + 1];
                float d;
                d = fmaf(-2.f, acc[nt][0], w20); acc[nt][0] = d; mna = fminf(mna, d);
                d = fmaf(-2.f, acc[nt][1], w21); acc[nt][1] = d; mna = fminf(mna, d);
                d = fmaf(-2.f, acc[nt][2], w20); acc[nt][2] = d; mnb = fminf(mnb, d);
                d = fmaf(-2.f, acc[nt][3], w21); acc[nt][3] = d; mnb = fminf(mnb, d);
            }
            #pragma unroll
            for (int o = 1; o <= 2; o <<= 1) {
                mna = fminf(mna, __shfl_xor_sync(0xffffffffu, mna, o));
                mnb = fminf(mnb, __shfl_xor_sync(0xffffffffu, mnb, o));
            }
            // Tighten with running global min (atomicMin returns OLD value, which
            // is >= final global min -> min(own, old) is a sound threshold base).
            float kna = mna, knb = mnb;
            if (tq == 0) {
                kna = fminf(kna, __int_as_float(atomicMin(&cminI[ra], __float_as_int(mna))));
                knb = fminf(knb, __int_as_float(atomicMin(&cminI[rb], __float_as_int(mnb))));
            }
            kna = __shfl_sync(0xffffffffu, kna, lane & ~3);
            knb = __shfl_sync(0xffffffffu, knb, lane & ~3);
            const float ta = kna + MARGIN, tb = knb + MARGIN;

            #pragma unroll
            for (int nt = 0; nt < 8; nt++) {
                int col = c * 128 + (half * 8 + nt) * 8 + tq * 2;
                #pragma unroll
                for (int v = 0; v < 2; v++) {
                    if (acc[nt][v] <= ta) {
                        int p = atomicAdd(&ccnt[ra], 1);
                        if (p < LIST_CAP)
                            clist[ra * LIST_CAP + p] = make_uint2(__float_as_uint(acc[nt][v]), col + v);
                    }
                    if (acc[nt][2 + v] <= tb) {
                        int p = atomicAdd(&ccnt[rb], 1);
                        if (p < LIST_CAP)
                            clist[rb * LIST_CAP + p] = make_uint2(__float_as_uint(acc[nt][2 + v]), col + v);
                    }
                }
            }
        }
    }

    __syncthreads();
    // Final refilter vs FINAL global min; overflow -> sentinel (P3 full scan)
    if (tid < 256) {
        int m = m0 + tid;
        float thr = __int_as_float(cminI[tid]) + MARGIN;
        int raw = ccnt[tid];
        if (raw > LIST_CAP) {
            g_ccnt[m] = 0x7FFFFFFF;
        } else {
            int out = 0;
            for (int i = 0; i < raw; i++) {
                uint2 e = clist[tid * LIST_CAP + i];
                if (__uint_as_float(e.x) <= thr)
                    g_cand[(size_t)m * CAND_MAX + (out++)] = e.y;
            }
            g_ccnt[m] = out;
        }
    }
}

// ---------------------------------------------------------------------------
// P3: exact fp32 rescore. One warp per query. Sentinel -> full exact scan.
__global__ __launch_bounds__(256) void vq_p3(const float* __restrict__ w) {
    const int wid = threadIdx.x >> 5, lane = threadIdx.x & 31;
    const int q = blockIdx.x * 8 + wid;
    const int cnt = g_ccnt[q];
    const float* xr = g_xt + (size_t)q * DN;
    const float x2v = g_x2[q];
    unsigned long long best = 0xFFFFFFFFFFFFFFFFULL;

    if (cnt != 0x7FFFFFFF) {
        for (int c = 0; c < cnt; c++) {
            unsigned int k = g_cand[(size_t)q * CAND_MAX + c];
            const float* wr = w + (size_t)k * DN;
            float s = 0.f;
            #pragma unroll
            for (int d = lane; d < DN; d += 32)
                s = fmaf(xr[d], wr[d], s);
            #pragma unroll
            for (int o = 16; o > 0; o >>= 1) s += __shfl_xor_sync(0xffffffffu, s, o);
            float d2 = __fadd_rn(__fsub_rn(x2v, __fmul_rn(2.0f, s)), g_w2[k]);
            unsigned int bits = __float_as_uint(d2);
            bits = (bits & 0x80000000u) ? ~bits : (bits | 0x80000000u);
            best = min(best, ((unsigned long long)bits << 32) | k);
        }
    } else {
        // Safety fallback: full exact scan (guarantees g_best is always set)
        for (int k = 0; k < KN; k++) {
            const float* wr = w + (size_t)k * DN;
            float s = 0.f;
            #pragma unroll
            for (int d = lane; d < DN; d += 32)
                s = fmaf(xr[d], wr[d], s);
            #pragma unroll
            for (int o = 16; o > 0; o >>= 1) s += __shfl_xor_sync(0xffffffffu, s, o);
            float d2 = __fadd_rn(__fsub_rn(x2v, __fmul_rn(2.0f, s)), g_w2[k]);
            unsigned int bits = __float_as_uint(d2);
            bits = (bits & 0x80000000u) ? ~bits : (bits | 0x80000000u);
            best = min(best, ((unsigned long long)bits << 32) | (unsigned int)k);
        }
    }
    if (lane == 0) g_best[q] = best;
}

// ---------------------------------------------------------------------------
// Gather: out[b,d,hw] = weight[idx[n], d]
__global__ void vq_gather(const float* __restrict__ w, float* __restrict__ out) {
    __shared__ float codes[32][DN + 1];
    const int b   = blockIdx.y;
    const int hw0 = blockIdx.x * 32;
    const int tid = threadIdx.x;  // 256
    for (int s = 0; s < 32; s++) {
        unsigned int idx = (unsigned int)(g_best[b * HWN + hw0 + s] & 0xFFFFFFFFu);
        codes[s][tid] = w[(size_t)idx * DN + tid];
    }
    __syncthreads();
    const int c    = tid & 31;
    const int dgrp = tid >> 5;
    float* ob = out + (size_t)b * DN * HWN + hw0;
    for (int d = dgrp; d < DN; d += 8)
        ob[(size_t)d * HWN + c] = codes[c][d];
}

// ---------------------------------------------------------------------------
extern "C" void kernel_launch(void* const* d_in, const int* in_sizes, int n_in,
                              void* d_out, int out_size) {
    const float* x = (const float*)d_in[0];   // [32,256,32,32] fp32
    const float* w = (const float*)d_in[1];   // [1024,256] fp32
    float* out = (float*)d_out;

    cudaFuncSetAttribute(vq_p1, cudaFuncAttributeMaxDynamicSharedMemorySize, SMEM_P1);

    vq_w2<<<KN / 8, 256>>>(w);                       // #1
    vq_wfrag<<<65536 / 256, 256>>>(w);               // #2
    {
        dim3 g(HWN / 32, DN / 32, BN);
        dim3 blk(32, 8);
        vq_xt<<<g, blk>>>(x);                        // #3
    }
    vq_p1<<<NN / 256, 512, SMEM_P1>>>();             // #4
    {
        dim3 g(HWN / 256, BN);
        vq_x2<<<g, 256>>>(x);                        // #5
    }
    vq_p3<<<NN / 8, 256>>>(w);                       // #6
    {
        dim3 g(HWN / 32, BN);
        vq_gather<<<g, 256>>>(w, out);               // #7
    }
}

// round 17
// speedup vs baseline: 2.4889x; 2.4889x over previous
#include <cuda_runtime.h>
#include <cuda_bf16.h>
#include <cstdint>

// Problem constants
#define BN   32
#define DN   256
#define KN   1024
#define HWN  1024
#define NN   32768

#define LIST_CAP 64
#define CAND_MAX 64
#define MARGIN   4.0e-3f   // > 2x worst-case bf16 score error (~1.6e-3)
#define SENTINEL 0x7FFFFFFF

// ---------------------------------------------------------------------------
// Device-global scratch (no allocation allowed)
__device__ unsigned long long g_best[NN];
__device__ float g_w2[KN];
__device__ float g_x2[NN];
__device__ __nv_bfloat16 g_xb[NN * DN];       // x bf16, PAIR-PERMUTED rows [n][pd]
__device__ float g_xt[NN * DN];               // x transposed fp32 [n][d]
__device__ int g_ccnt[NN];
__device__ unsigned int g_cand[NN * CAND_MAX];
__device__ uint2 g_bf[16 * 16 * 8 * 32];      // fragment-major codebook, 64-code chunks

// ---------------------------------------------------------------------------
__device__ __forceinline__ uint32_t smem_u32(const void* p) {
    uint32_t a;
    asm("{ .reg .u64 t; cvta.to.shared.u64 t, %1; cvt.u32.u64 %0, t; }" : "=r"(a) : "l"(p));
    return a;
}
__device__ __forceinline__ void mma16816(float* c, uint32_t a0, uint32_t a1,
                                         uint32_t a2, uint32_t a3,
                                         uint32_t b0, uint32_t b1) {
    asm volatile(
        "mma.sync.aligned.m16n8k16.row.col.f32.bf16.bf16.f32 "
        "{%0,%1,%2,%3}, {%4,%5,%6,%7}, {%8,%9}, {%0,%1,%2,%3};"
        : "+f"(c[0]), "+f"(c[1]), "+f"(c[2]), "+f"(c[3])
        : "r"(a0), "r"(a1), "r"(a2), "r"(a3), "r"(b0), "r"(b1));
}
#define CP16(saddr, gptr) \
    asm volatile("cp.async.cg.shared.global [%0], [%1], 16;" :: "r"(saddr), "l"(gptr) : "memory")
#define CP_COMMIT() asm volatile("cp.async.commit_group;" ::: "memory")
#define CP_WAIT0()  asm volatile("cp.async.wait_group 0;" ::: "memory")

__device__ __forceinline__ uint32_t pack_bf16x2(float lo, float hi) {
    uint16_t l = __bfloat16_as_ushort(__float2bfloat16(lo));
    uint16_t h = __bfloat16_as_ushort(__float2bfloat16(hi));
    return (uint32_t)l | ((uint32_t)h << 16);
}

// ---------------------------------------------------------------------------
// w2[k] = sum_d w[k,d]^2 (square-then-add, matching reference)
__global__ void vq_w2(const float* __restrict__ w) {
    int k = blockIdx.x * 8 + (threadIdx.x >> 5);
    int lane = threadIdx.x & 31;
    if (k >= KN) return;
    const float* row = w + (size_t)k * DN;
    float s = 0.f;
    #pragma unroll
    for (int d = lane; d < DN; d += 32) {
        float v = row[d];
        s = __fadd_rn(s, __fmul_rn(v, v));
    }
    #pragma unroll
    for (int o = 16; o > 0; o >>= 1) s += __shfl_xor_sync(0xffffffffu, s, o);
    if (lane == 0) g_w2[k] = s;
}

// x2[n] = sum_d x[b,d,hw]^2  (only P3 needs it; runs after P1)
__global__ void vq_x2(const float* __restrict__ x) {
    int b  = blockIdx.y;
    int hw = blockIdx.x * blockDim.x + threadIdx.x;
    const float* base = x + (size_t)b * DN * HWN + hw;
    float s = 0.f;
    #pragma unroll 8
    for (int d = 0; d < DN; d++) {
        float v = base[(size_t)d * HWN];
        s = __fadd_rn(s, __fmul_rn(v, v));
    }
    g_x2[b * HWN + hw] = s;
}

// Fragment-major codebook, 64-code chunks: g_bf[((c2*16+ks)*8+nt)*32+lane]
// k = c2*64 + nt*8 + gid; b0 = w[k][ks*16+2tq..], b1 = w[k][ks*16+2tq+8..]
__global__ void vq_wfrag(const float* __restrict__ w) {
    int i = blockIdx.x * 256 + threadIdx.x;   // 0..65535
    int lane = i & 31, nt = (i >> 5) & 7, ks = (i >> 8) & 15, c2 = i >> 12;
    int gid = lane >> 2, tq = lane & 3;
    int k = c2 * 64 + nt * 8 + gid;
    const float* row = w + (size_t)k * DN + ks * 16;
    uint32_t b0 = pack_bf16x2(row[2 * tq], row[2 * tq + 1]);
    uint32_t b1 = pack_bf16x2(row[2 * tq + 8], row[2 * tq + 9]);
    g_bf[i] = make_uint2(b0, b1);
}

// Transpose x[b][d][hw] -> g_xt[n][d] fp32 and g_xb[n][pd] bf16 pair-permuted:
// pd = ks*16 + tq*4 + hi*2 + par where d = ks*16 + hi*8 + tq*2 + par.
__global__ void vq_xt(const float* __restrict__ x) {
    __shared__ float t[32][33];
    int b   = blockIdx.z;
    int d0  = blockIdx.y * 32;
    int hw0 = blockIdx.x * 32;
    int tx = threadIdx.x, ty = threadIdx.y;  // 32 x 8
    #pragma unroll
    for (int r = 0; r < 4; r++)
        t[ty + 8 * r][tx] = x[(size_t)b * DN * HWN + (size_t)(d0 + ty + 8 * r) * HWN + hw0 + tx];
    __syncthreads();
    #pragma unroll
    for (int r = 0; r < 4; r++) {
        int n = b * HWN + hw0 + ty + 8 * r;
        int d = d0 + tx;
        float v = t[tx][ty + 8 * r];
        g_xt[(size_t)n * DN + d] = v;
        int pd = (d & ~15) | (((d >> 1) & 3) << 2) | (((d >> 3) & 1) << 1) | (d & 1);
        g_xb[(size_t)n * DN + pd] = __float2bfloat16(v);
    }
}

// ---------------------------------------------------------------------------
// P1: bf16 HMMA approx score s = w2 - 2*dot (rank-equivalent) + candidates.
// 256 CTAs x 256 thr (8 warps, 128 queries) -> 2 CTAs/SM, one wave.
// Warp -> 16 rows x full 64-code chunk (8 n-tiles). 16 chunks, cp.async x2.
// Lists hold idx only (4B): cap 64 fits in the 2-CTA/SM smem budget.
#define SMB0  0        // 32768
#define SMB1  32768    // 32768
#define SMW2  65536    // 4096
#define SMCM  69632    // 512
#define SMCC  70144    // 512
#define SMLS  70656    // 128*64*4 = 32768
#define SMEM_P1 103424

__global__ __launch_bounds__(256, 2) void vq_p1() {
    extern __shared__ __align__(16) char smem[];
    float* w2s   = (float*)(smem + SMW2);
    int*   cminI = (int*)(smem + SMCM);
    int*   ccnt  = (int*)(smem + SMCC);
    unsigned int* clist = (unsigned int*)(smem + SMLS);
    const uint32_t sb = smem_u32(smem);

    const int tid  = threadIdx.x;
    const int wid  = tid >> 5, lane = tid & 31;
    const int gid  = lane >> 2, tq = lane & 3;
    const int m0   = blockIdx.x * 128;
    const int ra   = wid * 16 + gid, rb = ra + 8;

    // Prologue: start async fill of B chunk 0 (32KB = 2048 x 16B)
    {
        const char* src = (const char*)g_bf;
        #pragma unroll
        for (int j = 0; j < 8; j++)
            CP16(sb + SMB0 + (tid + j * 256) * 16, src + (tid + j * 256) * 16);
        CP_COMMIT();
    }

    // Preload A fragments into registers (pair-permuted g_xb rows)
    uint2 afA[16], afB[16];
    {
        const __nv_bfloat16* pa = g_xb + (size_t)(m0 + ra) * DN + tq * 4;
        const __nv_bfloat16* pb = g_xb + (size_t)(m0 + rb) * DN + tq * 4;
        #pragma unroll
        for (int ks = 0; ks < 16; ks++) {
            afA[ks] = *(const uint2*)(pa + ks * 16);
            afB[ks] = *(const uint2*)(pb + ks * 16);
        }
    }

    #pragma unroll
    for (int i = tid; i < KN; i += 256) w2s[i] = g_w2[i];
    if (tid < 128) { cminI[tid] = 0x7F7FFFFF; ccnt[tid] = 0; }

    for (int c = 0; c < 16; c++) {
        CP_WAIT0();
        __syncthreads();   // B[c] + (c==0: inits) visible; prev compute done

        if (c < 15) {      // prefetch B[c+1] into the other buffer
            const char* src = (const char*)g_bf + (size_t)(c + 1) * 32768;
            uint32_t dstb = sb + (((c + 1) & 1) ? SMB1 : SMB0);
            #pragma unroll
            for (int j = 0; j < 8; j++)
                CP16(dstb + (tid + j * 256) * 16, src + (tid + j * 256) * 16);
            CP_COMMIT();
        }

        const uint2* Bbuf = (const uint2*)(smem + ((c & 1) ? SMB1 : SMB0));
        float acc[8][4];
        #pragma unroll
        for (int nt = 0; nt < 8; nt++)
            acc[nt][0] = acc[nt][1] = acc[nt][2] = acc[nt][3] = 0.f;

        #pragma unroll
        for (int ks = 0; ks < 16; ks++) {
            const uint2* bp = Bbuf + (size_t)(ks * 8) * 32 + lane;
            #pragma unroll
            for (int nt = 0; nt < 8; nt++) {
                uint2 b = bp[nt * 32];
                mma16816(acc[nt], afA[ks].x, afB[ks].x, afA[ks].y, afB[ks].y, b.x, b.y);
            }
        }

        // Scores s = w2 - 2*dot; chunk-local row mins (warp covers whole chunk)
        float mna = 3.4e38f, mnb = 3.4e38f;
        #pragma unroll
        for (int nt = 0; nt < 8; nt++) {
            int col = c * 64 + nt * 8 + tq * 2;
            float w20 = w2s[col], w21 = w2s[col + 1];
            float d;
            d = fmaf(-2.f, acc[nt][0], w20); acc[nt][0] = d; mna = fminf(mna, d);
            d = fmaf(-2.f, acc[nt][1], w21); acc[nt][1] = d; mna = fminf(mna, d);
            d = fmaf(-2.f, acc[nt][2], w20); acc[nt][2] = d; mnb = fminf(mnb, d);
            d = fmaf(-2.f, acc[nt][3], w21); acc[nt][3] = d; mnb = fminf(mnb, d);
        }
        #pragma unroll
        for (int o = 1; o <= 2; o <<= 1) {
            mna = fminf(mna, __shfl_xor_sync(0xffffffffu, mna, o));
            mnb = fminf(mnb, __shfl_xor_sync(0xffffffffu, mnb, o));
        }
        // Tighten with running global min (atomicMin returns OLD value >= final
        // global min -> min(own, old) is a sound (superset-preserving) base).
        float kna = mna, knb = mnb;
        if (tq == 0) {
            kna = fminf(kna, __int_as_float(atomicMin(&cminI[ra], __float_as_int(mna))));
            knb = fminf(knb, __int_as_float(atomicMin(&cminI[rb], __float_as_int(mnb))));
        }
        kna = __shfl_sync(0xffffffffu, kna, lane & ~3);
        knb = __shfl_sync(0xffffffffu, knb, lane & ~3);
        const float ta = kna + MARGIN, tb = knb + MARGIN;

        #pragma unroll
        for (int nt = 0; nt < 8; nt++) {
            int col = c * 64 + nt * 8 + tq * 2;
            #pragma unroll
            for (int v = 0; v < 2; v++) {
                if (acc[nt][v] <= ta) {
                    int p = atomicAdd(&ccnt[ra], 1);
                    if (p < LIST_CAP) clist[ra * LIST_CAP + p] = col + v;
                }
                if (acc[nt][2 + v] <= tb) {
                    int p = atomicAdd(&ccnt[rb], 1);
                    if (p < LIST_CAP) clist[rb * LIST_CAP + p] = col + v;
                }
            }
        }
    }

    __syncthreads();
    // Write lists out; overflow -> sentinel (P3b handles those queries)
    if (tid < 128) {
        int m = m0 + tid;
        int raw = ccnt[tid];
        if (raw > LIST_CAP) {
            g_ccnt[m] = SENTINEL;
        } else {
            for (int i = 0; i < raw; i++)
                g_cand[(size_t)m * CAND_MAX + i] = clist[tid * LIST_CAP + i];
            g_ccnt[m] = raw;
        }
    }
}

// ---------------------------------------------------------------------------
// P3a: exact fp32 rescore of candidate lists. One warp per query.
// Sentinel queries are SKIPPED (P3b owns them).
__global__ __launch_bounds__(256) void vq_p3(const float* __restrict__ w) {
    const int wid = threadIdx.x >> 5, lane = threadIdx.x & 31;
    const int q = blockIdx.x * 8 + wid;
    const int cnt = g_ccnt[q];
    if (cnt == SENTINEL) return;
    const float* xr = g_xt + (size_t)q * DN;
    const float x2v = g_x2[q];
    unsigned long long best = 0xFFFFFFFFFFFFFFFFULL;
    for (int c = 0; c < cnt; c++) {
        unsigned int k = g_cand[(size_t)q * CAND_MAX + c];
        const float* wr = w + (size_t)k * DN;
        float s = 0.f;
        #pragma unroll
        for (int d = lane; d < DN; d += 32)
            s = fmaf(xr[d], wr[d], s);
        #pragma unroll
        for (int o = 16; o > 0; o >>= 1) s += __shfl_xor_sync(0xffffffffu, s, o);
        float d2 = __fadd_rn(__fsub_rn(x2v, __fmul_rn(2.0f, s)), g_w2[k]);
        unsigned int bits = __float_as_uint(d2);
        bits = (bits & 0x80000000u) ? ~bits : (bits | 0x80000000u);
        best = min(best, ((unsigned long long)bits << 32) | k);
    }
    if (lane == 0) g_best[q] = best;
}

// P3b: overflow queries only -> block-cooperative exact 1024-code scan.
// 64 blocks x 256 thr; each block owns 512 query flags. Near-zero cost when
// no query overflows (expected case at cap 64).
__global__ __launch_bounds__(256) void vq_p3b(const float* __restrict__ w) {
    __shared__ float xs[DN];
    __shared__ unsigned long long wmin[8];
    const int tid = threadIdx.x, wid = tid >> 5, lane = tid & 31;
    const int q0 = blockIdx.x * 512;
    for (int qi = 0; qi < 512; qi++) {
        int q = q0 + qi;
        if (g_ccnt[q] != SENTINEL) continue;   // uniform per block
        if (tid < DN) xs[tid] = g_xt[(size_t)q * DN + tid];
        __syncthreads();
        const float x2v = g_x2[q];
        unsigned long long best = 0xFFFFFFFFFFFFFFFFULL;
        for (int k = wid; k < KN; k += 8) {
            const float* wr = w + (size_t)k * DN;
            float s = 0.f;
            #pragma unroll
            for (int d = lane; d < DN; d += 32)
                s = fmaf(xs[d], wr[d], s);
            #pragma unroll
            for (int o = 16; o > 0; o >>= 1) s += __shfl_xor_sync(0xffffffffu, s, o);
            float d2 = __fadd_rn(__fsub_rn(x2v, __fmul_rn(2.0f, s)), g_w2[k]);
            unsigned int bits = __float_as_uint(d2);
            bits = (bits & 0x80000000u) ? ~bits : (bits | 0x80000000u);
            best = min(best, ((unsigned long long)bits << 32) | (unsigned int)k);
        }
        if (lane == 0) wmin[wid] = best;
        __syncthreads();
        if (tid == 0) {
            unsigned long long b = wmin[0];
            #pragma unroll
            for (int i = 1; i < 8; i++) b = min(b, wmin[i]);
            g_best[q] = b;
        }
        __syncthreads();
    }
}

// ---------------------------------------------------------------------------
// Gather: out[b,d,hw] = weight[idx[n], d]
__global__ void vq_gather(const float* __restrict__ w, float* __restrict__ out) {
    __shared__ float codes[32][DN + 1];
    const int b   = blockIdx.y;
    const int hw0 = blockIdx.x * 32;
    const int tid = threadIdx.x;  // 256
    for (int s = 0; s < 32; s++) {
        unsigned int idx = (unsigned int)(g_best[b * HWN + hw0 + s] & 0xFFFFFFFFu);
        codes[s][tid] = w[(size_t)idx * DN + tid];
    }
    __syncthreads();
    const int c    = tid & 31;
    const int dgrp = tid >> 5;
    float* ob = out + (size_t)b * DN * HWN + hw0;
    for (int d = dgrp; d < DN; d += 8)
        ob[(size_t)d * HWN + c] = codes[c][d];
}

// ---------------------------------------------------------------------------
extern "C" void kernel_launch(void* const* d_in, const int* in_sizes, int n_in,
                              void* d_out, int out_size) {
    const float* x = (const float*)d_in[0];   // [32,256,32,32] fp32
    const float* w = (const float*)d_in[1];   // [1024,256] fp32
    float* out = (float*)d_out;

    cudaFuncSetAttribute(vq_p1, cudaFuncAttributeMaxDynamicSharedMemorySize, SMEM_P1);

    vq_w2<<<KN / 8, 256>>>(w);                       // #1
    vq_wfrag<<<65536 / 256, 256>>>(w);               // #2
    {
        dim3 g(HWN / 32, DN / 32, BN);
        dim3 blk(32, 8);
        vq_xt<<<g, blk>>>(x);                        // #3
    }
    vq_p1<<<NN / 128, 256, SMEM_P1>>>();             // #4
    {
        dim3 g(HWN / 256, BN);
        vq_x2<<<g, 256>>>(x);                        // #5
    }
    vq_p3<<<NN / 8, 256>>>(w);                       // #6
    vq_p3b<<<64, 256>>>(w);                          // #7 (overflow-only)
    {
        dim3 g(HWN / 32, BN);
        vq_gather<<<g, 256>>>(w, out);               // #8
    }
}